// round 9
// baseline (speedup 1.0000x reference)
#include <cuda_runtime.h>
#include <cstdint>

// CrossMerge3D: out[b,c,i,j,k] = ( sum of 12 scans in 3 orientations ) / 12
//   family i (s=0..3):  n = i*1024 + j*32 + k   (fwd s0,s1; flipped s2,s3)
//   family j (s=4..7):  n = j*1024 + k*32 + i
//   family k (s=8..11): n = k*1024 + i*32 + j
//
// Block = (b, c, i-slab of 4), 256 threads. WARP-SPECIALIZED front:
//   warps 0-3: all of family i -> acc1 (plain stores)
//   warps 4-7: all of family j -> acc2 (plain stores)   [concurrent, no RMW]
// barrier -> phase C: all warps, acc1 += family k (only RMW phase)
// barrier -> phase D: out = (acc1+acc2)/12, float4 streaming stores.
// One less barrier than the 61.6us variant, RMW-free front section, and both
// load streams live simultaneously so smem tails never drain the DRAM pipe.

#define DD      32
#define NVOL    32768            // 32^3
#define CCH     96
#define CN      (CCH * NVOL)     // 3145728
#define SLAB_I  4
#define NSLAB   (DD / SLAB_I)    // 8
#define SLAB_N  (SLAB_I * DD * DD)   // 4096
#define THREADS 256
#define HALF    128
#define CHUNKS  (SLAB_N / 4)     // 1024 float4-chunks per family
#define ITERS_AB (CHUNKS / HALF)     // 8 (half the threads per family)
#define ITERS_CD (CHUNKS / THREADS)  // 4

// padded smem index: injective (per-ii span 0..1054 < 1060),
// bank(f) = (4*ii + j + k) mod 32  (1060 mod 32 = 4, 33 mod 32 = 1)
#define STRIDE_II 1060
#define REGION    (3 * STRIDE_II + 31 * 33 + 31 + 2)   // 4236 floats
__device__ __forceinline__ int fidx(int ii, int j, int k) {
    return ii * STRIDE_II + j * 33 + k;
}

__global__ __launch_bounds__(THREADS)
void cross_merge3d_kernel(const float* __restrict__ ys, float* __restrict__ out) {
    __shared__ float acc1[REGION];   // family i, then += family k
    __shared__ float acc2[REGION];   // family j

    const int bid = blockIdx.x;
    const int a   = bid & (NSLAB - 1);        // i-slab (0..7)
    const int c   = (bid >> 3) % CCH;
    const int b   = bid / (NSLAB * CCH);
    const int tid = threadIdx.x;

    const float* base = ys + (size_t)b * (12 * (size_t)CN) + (size_t)c * NVOL;

    if (tid < HALF) {
        // ---------- Warps 0-3: family i (s = 0..3) -> acc1 ----------
        const float* q0 = base + 0 * (size_t)CN;
        const float* q1 = base + 1 * (size_t)CN;
        const float* q2 = base + 2 * (size_t)CN;
        const float* q3 = base + 3 * (size_t)CN;
        #pragma unroll 4
        for (int it = 0; it < ITERS_AB; it++) {
            int chunk   = it * HALF + tid;
            int n_local = chunk * 4;
            int ii = n_local >> 10;               // 0..3
            int j  = (n_local >> 5) & 31;
            int k  = n_local & 31;
            int n_g = a * SLAB_N + n_local;
            float4 f0 = *(const float4*)(q0 + n_g);
            float4 f1 = *(const float4*)(q1 + n_g);
            int r_g = NVOL - 4 - n_g;
            float4 r2 = *(const float4*)(q2 + r_g);
            float4 r3 = *(const float4*)(q3 + r_g);
            int f = fidx(ii, j, k);
            acc1[f + 0] = f0.x + f1.x + r2.w + r3.w;
            acc1[f + 1] = f0.y + f1.y + r2.z + r3.z;
            acc1[f + 2] = f0.z + f1.z + r2.y + r3.y;
            acc1[f + 3] = f0.w + f1.w + r2.x + r3.x;
        }
    } else {
        // ---------- Warps 4-7: family j (s = 4..7) -> acc2 ----------
        // n = j*1024 + k*32 + i; one float4 i-chunk per (j,k): i = 4a..4a+3
        const float* q4 = base + 4 * (size_t)CN;
        const float* q5 = base + 5 * (size_t)CN;
        const float* q6 = base + 6 * (size_t)CN;
        const float* q7 = base + 7 * (size_t)CN;
        const int t = tid - HALF;
        #pragma unroll 4
        for (int it = 0; it < ITERS_AB; it++) {
            int chunk = it * HALF + t;
            int k  = chunk & 31;
            int j  = chunk >> 5;
            int m  = j * 1024 + k * 32 + a * SLAB_I;
            float4 f4 = *(const float4*)(q4 + m);
            float4 f5 = *(const float4*)(q5 + m);
            int r_m = NVOL - 4 - m;
            float4 r6 = *(const float4*)(q6 + r_m);
            float4 r7 = *(const float4*)(q7 + r_m);
            acc2[fidx(0, j, k)] = f4.x + f5.x + r6.w + r7.w;
            acc2[fidx(1, j, k)] = f4.y + f5.y + r6.z + r7.z;
            acc2[fidx(2, j, k)] = f4.z + f5.z + r6.y + r7.y;
            acc2[fidx(3, j, k)] = f4.w + f5.w + r6.x + r7.x;
        }
    }
    __syncthreads();

    // ---------------- Phase C: family k (s = 8..11), acc1 += ----------------
    // n = k*1024 + i*32 + j
    {
        const float* q8  = base + 8  * (size_t)CN;
        const float* q9  = base + 9  * (size_t)CN;
        const float* q10 = base + 10 * (size_t)CN;
        const float* q11 = base + 11 * (size_t)CN;
        #pragma unroll
        for (int it = 0; it < ITERS_CD; it++) {
            int chunk = it * THREADS + tid;
            int j4 = chunk & 7;                 // j = 4*j4 + e
            int k  = (chunk >> 3) & 31;
            int ii = chunk >> 8;                // 0..3
            int m  = k * 1024 + (a * SLAB_I + ii) * 32 + 4 * j4;
            float4 f8 = *(const float4*)(q8  + m);
            float4 f9 = *(const float4*)(q9  + m);
            int r_m = NVOL - 4 - m;
            float4 rA = *(const float4*)(q10 + r_m);
            float4 rB = *(const float4*)(q11 + r_m);
            int jb = 4 * j4;
            acc1[fidx(ii, jb + 0, k)] += f8.x + f9.x + rA.w + rB.w;
            acc1[fidx(ii, jb + 1, k)] += f8.y + f9.y + rA.z + rB.z;
            acc1[fidx(ii, jb + 2, k)] += f8.z + f9.z + rA.y + rB.y;
            acc1[fidx(ii, jb + 3, k)] += f8.w + f9.w + rA.x + rB.x;
        }
    }
    __syncthreads();

    // ---------------- Phase D: sum regions, scale, float4 streaming store ----------------
    {
        float* ob = out + ((size_t)b * CCH + c) * NVOL + a * SLAB_N;
        const float s = 1.0f / 12.0f;
        #pragma unroll
        for (int it = 0; it < ITERS_CD; it++) {
            int chunk   = it * THREADS + tid;
            int n_local = chunk * 4;
            int ii = n_local >> 10;
            int j  = (n_local >> 5) & 31;
            int k  = n_local & 31;
            int f = fidx(ii, j, k);
            float4 o;
            o.x = (acc1[f + 0] + acc2[f + 0]) * s;
            o.y = (acc1[f + 1] + acc2[f + 1]) * s;
            o.z = (acc1[f + 2] + acc2[f + 2]) * s;
            o.w = (acc1[f + 3] + acc2[f + 3]) * s;
            __stcs((float4*)(ob + n_local), o);
        }
    }
}

extern "C" void kernel_launch(void* const* d_in, const int* in_sizes, int n_in,
                              void* d_out, int out_size) {
    const float* ys = (const float*)d_in[0];
    float* out = (float*)d_out;
    // grid = B * C * slabs = 2 * 96 * 8 = 1536
    cross_merge3d_kernel<<<1536, THREADS>>>(ys, out);
}

// round 10
// speedup vs baseline: 1.2318x; 1.2318x over previous
#include <cuda_runtime.h>
#include <cstdint>

// CrossMerge3D: out[b,c,i,j,k] = ( sum of 12 scans in 3 orientations ) / 12
//   family i (s=0..3):  n = i*1024 + j*32 + k   (fwd s0,s1; flipped s2,s3)
//   family j (s=4..7):  n = j*1024 + k*32 + i
//   family k (s=8..11): n = k*1024 + i*32 + j
//
// Block = (b, c, i-slab of 4), 256 threads, 17KB smem, 6 blocks/SM.
// Phase order chosen so the contiguous-output family (i) runs LAST and
// carries the fused epilogue with float4 streaming stores:
//   1. family j -> acc =   (plain stores, no RMW)
//   2. family k -> acc +=  (only RMW pass)
//   3. family i loads + out = (acc + fam_i)/12, float4 __stcs
// vs the 61.6us variant: one less barrier, one less smem RMW pass, no
// separate epilogue pass — same load/store coalescing everywhere.

#define DD      32
#define NVOL    32768            // 32^3
#define CCH     96
#define CN      (CCH * NVOL)     // 3145728
#define SLAB_I  4
#define NSLAB   (DD / SLAB_I)    // 8
#define SLAB_N  (SLAB_I * DD * DD)   // 4096
#define THREADS 256
#define CHUNKS  (SLAB_N / 4)     // 1024 float4-chunks per phase
#define ITERS   (CHUNKS / THREADS)   // 4

// padded smem index: injective (per-ii span 0..1054 < 1060),
// bank(f) = (4*ii + j + k) mod 32  (1060 mod 32 = 4, 33 mod 32 = 1)
#define STRIDE_II 1060
__device__ __forceinline__ int fidx(int ii, int j, int k) {
    return ii * STRIDE_II + j * 33 + k;
}

__global__ __launch_bounds__(THREADS)
void cross_merge3d_kernel(const float* __restrict__ ys, float* __restrict__ out) {
    __shared__ float acc[3 * STRIDE_II + 31 * 33 + 31 + 2];   // 4236 floats (~17KB)

    const int bid = blockIdx.x;
    const int a   = bid & (NSLAB - 1);        // i-slab (0..7)
    const int c   = (bid >> 3) % CCH;
    const int b   = bid / (NSLAB * CCH);
    const int tid = threadIdx.x;

    const float* base = ys + (size_t)b * (12 * (size_t)CN) + (size_t)c * NVOL;

    // ---------------- Phase 1: family j (s = 4..7), init accumulator ----------------
    // n = j*1024 + k*32 + i; one float4 i-chunk per (j,k): i = 4a .. 4a+3
    {
        const float* q4 = base + 4 * (size_t)CN;
        const float* q5 = base + 5 * (size_t)CN;
        const float* q6 = base + 6 * (size_t)CN;
        const float* q7 = base + 7 * (size_t)CN;
        #pragma unroll
        for (int it = 0; it < ITERS; it++) {
            int chunk = it * THREADS + tid;
            int k  = chunk & 31;
            int j  = chunk >> 5;
            int m  = j * 1024 + k * 32 + a * SLAB_I;
            float4 f4 = *(const float4*)(q4 + m);
            float4 f5 = *(const float4*)(q5 + m);
            int r_m = NVOL - 4 - m;
            float4 r6 = *(const float4*)(q6 + r_m);
            float4 r7 = *(const float4*)(q7 + r_m);
            acc[fidx(0, j, k)] = f4.x + f5.x + r6.w + r7.w;
            acc[fidx(1, j, k)] = f4.y + f5.y + r6.z + r7.z;
            acc[fidx(2, j, k)] = f4.z + f5.z + r6.y + r7.y;
            acc[fidx(3, j, k)] = f4.w + f5.w + r6.x + r7.x;
        }
    }
    __syncthreads();

    // ---------------- Phase 2: family k (s = 8..11), acc += ----------------
    // n = k*1024 + i*32 + j
    {
        const float* q8  = base + 8  * (size_t)CN;
        const float* q9  = base + 9  * (size_t)CN;
        const float* q10 = base + 10 * (size_t)CN;
        const float* q11 = base + 11 * (size_t)CN;
        #pragma unroll
        for (int it = 0; it < ITERS; it++) {
            int chunk = it * THREADS + tid;
            int j4 = chunk & 7;                 // j = 4*j4 + e
            int k  = (chunk >> 3) & 31;
            int ii = chunk >> 8;                // 0..3
            int m  = k * 1024 + (a * SLAB_I + ii) * 32 + 4 * j4;
            float4 f8 = *(const float4*)(q8  + m);
            float4 f9 = *(const float4*)(q9  + m);
            int r_m = NVOL - 4 - m;
            float4 rA = *(const float4*)(q10 + r_m);
            float4 rB = *(const float4*)(q11 + r_m);
            int jb = 4 * j4;
            acc[fidx(ii, jb + 0, k)] += f8.x + f9.x + rA.w + rB.w;
            acc[fidx(ii, jb + 1, k)] += f8.y + f9.y + rA.z + rB.z;
            acc[fidx(ii, jb + 2, k)] += f8.z + f9.z + rA.y + rB.y;
            acc[fidx(ii, jb + 3, k)] += f8.w + f9.w + rA.x + rB.x;
        }
    }
    __syncthreads();

    // ---------------- Phase 3: family i (s = 0..3) + fused epilogue ----------------
    // n = i*1024 + j*32 + k. Threads own contiguous output cells ->
    // float4 streaming stores, same shape as the proven phase-D epilogue.
    {
        const float* q0 = base + 0 * (size_t)CN;
        const float* q1 = base + 1 * (size_t)CN;
        const float* q2 = base + 2 * (size_t)CN;
        const float* q3 = base + 3 * (size_t)CN;
        float* ob = out + ((size_t)b * CCH + c) * NVOL + a * SLAB_N;
        const float s = 1.0f / 12.0f;
        #pragma unroll
        for (int it = 0; it < ITERS; it++) {
            int chunk   = it * THREADS + tid;
            int n_local = chunk * 4;
            int ii = n_local >> 10;               // 0..3
            int j  = (n_local >> 5) & 31;
            int k  = n_local & 31;
            int n_g = a * SLAB_N + n_local;
            float4 f0 = *(const float4*)(q0 + n_g);
            float4 f1 = *(const float4*)(q1 + n_g);
            int r_g = NVOL - 4 - n_g;
            float4 r2 = *(const float4*)(q2 + r_g);
            float4 r3 = *(const float4*)(q3 + r_g);
            int f = fidx(ii, j, k);
            float4 o;
            o.x = (acc[f + 0] + f0.x + f1.x + r2.w + r3.w) * s;
            o.y = (acc[f + 1] + f0.y + f1.y + r2.z + r3.z) * s;
            o.z = (acc[f + 2] + f0.z + f1.z + r2.y + r3.y) * s;
            o.w = (acc[f + 3] + f0.w + f1.w + r2.x + r3.x) * s;
            __stcs((float4*)(ob + n_local), o);
        }
    }
}

extern "C" void kernel_launch(void* const* d_in, const int* in_sizes, int n_in,
                              void* d_out, int out_size) {
    const float* ys = (const float*)d_in[0];
    float* out = (float*)d_out;
    // grid = B * C * slabs = 2 * 96 * 8 = 1536
    cross_merge3d_kernel<<<1536, THREADS>>>(ys, out);
}